// round 4
// baseline (speedup 1.0000x reference)
#include <cuda_runtime.h>

// LocalVariation: out[b, k, y, x] = x[b,0,y,x] - x_pad[b,0,y+i,x+j]
// 24 off-center (i,j) in 5x5 window, replicate padding.
// x [16,1,512,512] f32 -> out [16,24,512,512] f32.
//
// R4: raise occupancy to deepen store MLP. TYO=8 (1 row/thread, no rolling),
// __launch_bounds__(256,6) -> target <=42 regs, 6 blocks/SM (~888 resident).
// Grid 4096 tiles keeps wave-tail loss ~8%. float4 streaming stores.

#define HH 512
#define WW 512
#define NB 16
#define NC 24
#define TX 128   // tile width (32 threads x float4)
#define TYO 8    // tile height (8 thread-rows x 1 row)
#define SW 132   // TX + 4 halo
#define SH 12    // TYO + 4 halo

__global__ __launch_bounds__(256, 6)
void local_variation_kernel(const float* __restrict__ x, float* __restrict__ out) {
    __shared__ float s[SH][SW];

    const int tid = threadIdx.y * 32 + threadIdx.x;
    const int x0 = blockIdx.x * TX;
    const int y0 = blockIdx.y * TYO;
    const int b  = blockIdx.z;

    const float* __restrict__ xb = x + (size_t)b * HH * WW;

    // Cooperative halo load with replicate-pad clamping. SH*SW = 1584 elems.
    #pragma unroll
    for (int idx = tid; idx < SH * SW; idx += 256) {
        int r = idx / SW;
        int c = idx - r * SW;
        int gy = min(max(y0 + r - 2, 0), HH - 1);
        int gx = min(max(x0 + c - 2, 0), WW - 1);
        s[r][c] = xb[gy * WW + gx];
    }
    __syncthreads();

    const int sx = threadIdx.x * 4;   // tile-local col of first pixel
    const int sy = threadIdx.y;       // tile-local output row

    // 5-row x 8-float neighborhood (two aligned float4 per row).
    float w[5][8];
    #pragma unroll
    for (int i = 0; i < 5; i++) {
        float4 lo = *reinterpret_cast<const float4*>(&s[sy + i][sx]);
        float4 hi = *reinterpret_cast<const float4*>(&s[sy + i][sx + 4]);
        w[i][0] = lo.x; w[i][1] = lo.y; w[i][2] = lo.z; w[i][3] = lo.w;
        w[i][4] = hi.x; w[i][5] = hi.y; w[i][6] = hi.z; w[i][7] = hi.w;
    }

    const float c0 = w[2][2], c1 = w[2][3], c2 = w[2][4], c3 = w[2][5];

    const int gy = y0 + sy;
    const int gx = x0 + sx;
    float* __restrict__ ob = out + (((size_t)b * NC) * HH + gy) * WW + gx;
    const size_t plane = (size_t)HH * WW;

    int k = 0;
    #pragma unroll
    for (int i = 0; i < 5; i++) {
        #pragma unroll
        for (int j = 0; j < 5; j++) {
            if (i == 2 && j == 2) continue;
            float4 o;
            o.x = c0 - w[i][j + 0];
            o.y = c1 - w[i][j + 1];
            o.z = c2 - w[i][j + 2];
            o.w = c3 - w[i][j + 3];
            __stcs(reinterpret_cast<float4*>(ob + (size_t)k * plane), o);
            k++;
        }
    }
}

extern "C" void kernel_launch(void* const* d_in, const int* in_sizes, int n_in,
                              void* d_out, int out_size) {
    const float* x = (const float*)d_in[0];
    float* out = (float*)d_out;
    dim3 block(32, 8, 1);
    dim3 grid(WW / TX, HH / TYO, NB);   // 4 x 64 x 16 = 4096 blocks
    local_variation_kernel<<<grid, block>>>(x, out);
}

// round 5
// speedup vs baseline: 1.3140x; 1.3140x over previous
#include <cuda_runtime.h>

// LocalVariation: out[b, k, y, x] = x[b,0,y,x] - x_pad[b,0,y+i,x+j]
// 24 off-center (i,j) in 5x5 window, replicate padding.
// x [16,1,512,512] f32 -> out [16,24,512,512] f32.
//
// R5 = R3 (128-wide tile, rolling 2-row/thread window, float4 __stcs) with
// NON-UNIFORM tile heights to kill the wave-quantization tail:
//   per 512-row strip: 2 tiles of 16 rows + 32 tiles of 15 rows (34 tiles).
//   grid = 4 x 34 x 16 = 2176 blocks; 2176 / 740 resident = 2.94 -> ~2% tail
//   (R3: 2048/740 = 2.77 -> ceil 3 -> 7.7% tail).
// __launch_bounds__(256,5): regs must stay <=51 to keep 5 blocks/SM.

#define HH 512
#define WW 512
#define NB 16
#define NC 24
#define TX 128   // tile width (32 threads x float4)
#define SW 132   // TX + 4 halo
#define SHMAX 20 // max tile height (16) + 4 halo

__global__ __launch_bounds__(256, 5)
void local_variation_kernel(const float* __restrict__ x, float* __restrict__ out) {
    __shared__ float s[SHMAX][SW];

    const int tid = threadIdx.y * 32 + threadIdx.x;
    const int x0 = blockIdx.x * TX;
    const int by = blockIdx.y;
    const int b  = blockIdx.z;

    // Non-uniform tile heights: by 0,1 -> 16 rows; by 2..33 -> 15 rows.
    const int h  = (by < 2) ? 16 : 15;
    const int y0 = (by < 2) ? (16 * by) : (32 + 15 * (by - 2));
    const int sh = h + 4;

    const float* __restrict__ xb = x + (size_t)b * HH * WW;

    // Cooperative halo load with replicate-pad clamping. sh*SW elems.
    for (int idx = tid; idx < sh * SW; idx += 256) {
        int r = idx / SW;
        int c = idx - r * SW;
        int gy = min(max(y0 + r - 2, 0), HH - 1);
        int gx = min(max(x0 + c - 2, 0), WW - 1);
        s[r][c] = xb[gy * WW + gx];
    }
    __syncthreads();

    const int sx = threadIdx.x * 4;    // tile-local col of first pixel
    const int rb = threadIdx.y * 2;    // first output row (tile-local)
    // rb in [0,14]; row rb always < h (h>=15). Row rb+1 valid iff rb+1 < h.
    const bool row1 = (rb + 1) < h;    // warp-uniform (threadIdx.y == warp id)

    // 5-row x 8-float rolling register window.
    // Invariant at step t: slot (t+i)%5 holds smem row rb+t+i.
    float w[5][8];
    #pragma unroll
    for (int i = 0; i < 5; i++) {
        float4 lo = *reinterpret_cast<const float4*>(&s[rb + i][sx]);
        float4 hi = *reinterpret_cast<const float4*>(&s[rb + i][sx + 4]);
        w[i][0] = lo.x; w[i][1] = lo.y; w[i][2] = lo.z; w[i][3] = lo.w;
        w[i][4] = hi.x; w[i][5] = hi.y; w[i][6] = hi.z; w[i][7] = hi.w;
    }

    const int gy0 = y0 + rb;
    const int gx  = x0 + sx;
    float* __restrict__ ob = out + (((size_t)b * NC) * HH + gy0) * WW + gx;
    const size_t plane = (size_t)HH * WW;

    // ---- row 0 (always valid) ----
    {
        const float* cw = w[2];
        const float c0 = cw[2], c1 = cw[3], c2 = cw[4], c3 = cw[5];
        int k = 0;
        #pragma unroll
        for (int i = 0; i < 5; i++) {
            const float* rr = w[i];
            #pragma unroll
            for (int j = 0; j < 5; j++) {
                if (i == 2 && j == 2) continue;
                float4 o;
                o.x = c0 - rr[j + 0];
                o.y = c1 - rr[j + 1];
                o.z = c2 - rr[j + 2];
                o.w = c3 - rr[j + 3];
                __stcs(reinterpret_cast<float4*>(ob + (size_t)k * plane), o);
                k++;
            }
        }
    }

    // ---- roll + row 1 (warp-uniform predicate) ----
    if (row1) {
        // slot 0 (held row rb) <- smem row rb+5
        {
            float4 lo = *reinterpret_cast<const float4*>(&s[rb + 5][sx]);
            float4 hi = *reinterpret_cast<const float4*>(&s[rb + 5][sx + 4]);
            float* d = w[0];
            d[0] = lo.x; d[1] = lo.y; d[2] = lo.z; d[3] = lo.w;
            d[4] = hi.x; d[5] = hi.y; d[6] = hi.z; d[7] = hi.w;
        }
        const float* cw = w[3];   // (1+2)%5
        const float c0 = cw[2], c1 = cw[3], c2 = cw[4], c3 = cw[5];
        float* __restrict__ orow = ob + WW;
        int k = 0;
        #pragma unroll
        for (int i = 0; i < 5; i++) {
            const float* rr = w[(1 + i) % 5];
            #pragma unroll
            for (int j = 0; j < 5; j++) {
                if (i == 2 && j == 2) continue;
                float4 o;
                o.x = c0 - rr[j + 0];
                o.y = c1 - rr[j + 1];
                o.z = c2 - rr[j + 2];
                o.w = c3 - rr[j + 3];
                __stcs(reinterpret_cast<float4*>(orow + (size_t)k * plane), o);
                k++;
            }
        }
    }
}

extern "C" void kernel_launch(void* const* d_in, const int* in_sizes, int n_in,
                              void* d_out, int out_size) {
    const float* x = (const float*)d_in[0];
    float* out = (float*)d_out;
    dim3 block(32, 8, 1);
    dim3 grid(WW / TX, 34, NB);   // 4 x 34 x 16 = 2176 blocks
    local_variation_kernel<<<grid, block>>>(x, out);
}